// round 15
// baseline (speedup 1.0000x reference)
#include <cuda_runtime.h>

#define NN 100000
#define NE 1600000
#define NG 16
#define PERG (NE / NG)      // 100000 edges per graph segment
#define TSTEP (NN / NG)     // 6250 threshold step
#define BN_EPS 1e-5f
#define MAXDEG 64
#define FULLMASK 0xffffffffu

typedef unsigned long long u64;

// ---------------- scratch ----------------------------------------------------
__device__ float g_h1[NN * 64];     // MLP1 output (post-relu, pre-BN)
__device__ int   g_adj[NN * MAXDEG];
__device__ int   g_ideg[NN];
__device__ float g_stats1[128];
__device__ float g_stats2[128];
__device__ float g_gsum[NG * 64];
__device__ float g_cnt[NG];

// ---------------- helpers ----------------------------------------------------
__device__ __forceinline__ u64 pk2(float lo, float hi) {
    u64 r; asm("mov.b64 %0, {%1,%2};" : "=l"(r) : "f"(lo), "f"(hi)); return r;
}
__device__ __forceinline__ void upk2(u64 v, float& a, float& b) {
    asm("mov.b64 {%0,%1}, %2;" : "=f"(a), "=f"(b) : "l"(v));
}
__device__ __forceinline__ u64 ffma2(u64 a, u64 b, u64 c) {
    u64 d; asm("fma.rn.f32x2 %0, %1, %2, %3;" : "=l"(d) : "l"(a), "l"(b), "l"(c));
    return d;
}
__device__ __forceinline__ u64 add2(u64 a, u64 b) {
    u64 d; asm("add.rn.f32x2 %0, %1, %2;" : "=l"(d) : "l"(a), "l"(b));
    return d;
}
__device__ __forceinline__ u64 relu2(u64 v) {
    float a, b; upk2(v, a, b);
    return pk2(fmaxf(a, 0.f), fmaxf(b, 0.f));
}

// Table: per warp, 64 rows x 10 u64 (16 nodes = 8 pairs, stride 20 floats).
#define ROW_U64 10
#define TBL_U64 (64 * ROW_U64)          // 640 u64 per warp
#define TILE_N 16
#define NTILES (NN / TILE_N)            // 6250 exact

// ---------------- small kernels ----------------------------------------------
__global__ void zero_kernel() {
    int i = blockIdx.x * blockDim.x + threadIdx.x;
    if (i < NN) g_ideg[i] = 0;
    if (i < 128) { g_stats1[i] = 0.f; g_stats2[i] = 0.f; }
    if (i < NG * 64) g_gsum[i] = 0.f;
    if (i < NG) g_cnt[i] = 0.f;
}

__global__ void adj_build_kernel(const int* __restrict__ ei) {
    int e = blockIdx.x * blockDim.x + threadIdx.x;
    if (e >= NE) return;
    int th = (e / PERG) * TSTEP;
    int s = __ldg(&ei[e]);
    int d = __ldg(&ei[NE + e]);
    if (s < th || d < th) return;
    int slot = atomicAdd(&g_ideg[d], 1);
    if (slot < MAXDEG) g_adj[d * MAXDEG + slot] = s;
}

// High-MLP gather of one node pair (64-dim rows). All loads unconditional
// (indices clamped to node 0 -> always valid), adds predicated (warp-uniform).
__device__ __forceinline__ void gather_pair(
    const float* __restrict__ feat, int nA, int nB, int degA, int degB,
    int lane, float& aA0, float& aA1, float& aB0, float& aB1) {
    const int* adjA = g_adj + nA * MAXDEG;
    const int* adjB = g_adj + nB * MAXDEG;
    aA0 = __ldg(&feat[nA * 64 + lane]);
    aA1 = __ldg(&feat[nA * 64 + lane + 32]);
    aB0 = __ldg(&feat[nB * 64 + lane]);
    aB1 = __ldg(&feat[nB * 64 + lane + 32]);
    int dmax = max(degA, degB);
    for (int j = 0; j < dmax; j += 2) {
        bool pA0 = (j < degA), pA1 = (j + 1 < degA);
        bool pB0 = (j < degB), pB1 = (j + 1 < degB);
        int sA0 = pA0 ? __ldg(&adjA[j]) : 0;
        int sA1 = pA1 ? __ldg(&adjA[j + 1]) : 0;
        int sB0 = pB0 ? __ldg(&adjB[j]) : 0;
        int sB1 = pB1 ? __ldg(&adjB[j + 1]) : 0;
        float vA0l = __ldg(&feat[sA0 * 64 + lane]);
        float vA0h = __ldg(&feat[sA0 * 64 + lane + 32]);
        float vA1l = __ldg(&feat[sA1 * 64 + lane]);
        float vA1h = __ldg(&feat[sA1 * 64 + lane + 32]);
        float vB0l = __ldg(&feat[sB0 * 64 + lane]);
        float vB0h = __ldg(&feat[sB0 * 64 + lane + 32]);
        float vB1l = __ldg(&feat[sB1 * 64 + lane]);
        float vB1h = __ldg(&feat[sB1 * 64 + lane + 32]);
        if (pA0) { aA0 += vA0l; aA1 += vA0h; }
        if (pA1) { aA0 += vA1l; aA1 += vA1h; }
        if (pB0) { aB0 += vB0l; aB1 += vB0h; }
        if (pB1) { aB0 += vB1l; aB1 += vB1h; }
    }
}

// ---------------- MLP1 (fused gather): 64 -> relu 32 -> relu 64 --------------
__global__ __launch_bounds__(256, 4) void mlp1_kernel(
    const float* __restrict__ xfeat,
    const float* __restrict__ W1a, const float* __restrict__ b1a,
    const float* __restrict__ W1b, const float* __restrict__ b1b) {
    extern __shared__ u64 sm[];
    u64* tables = sm;                          // 8 * 640 u64 (40KB)
    float* sWa = (float*)(sm + 8 * TBL_U64);   // 2048 f32
    float* sWb = sWa + 2048;                   // 2048 f32

    for (int i = threadIdx.x; i < 2048; i += 256) {
        sWa[i] = W1a[i];
        sWb[i] = W1b[i];
    }
    __syncthreads();

    int lane = threadIdx.x & 31;
    u64* xs = tables + (threadIdx.x >> 5) * TBL_U64;
    float* xsf = (float*)xs;

    int warp = (blockIdx.x * 256 + threadIdx.x) >> 5;
    int nw = (gridDim.x * 256) >> 5;

    float bav = b1a[lane];
    u64 bA = pk2(bav, bav);
    float bl = b1b[lane], bh = b1b[lane + 32];
    u64 bbL = pk2(bl, bl), bbH = pk2(bh, bh);

    u64 sA = 0, sB = 0, qA = 0, qB = 0;

    for (int t = warp; t < NTILES; t += nw) {
        int nb = t * TILE_N;
        // ---- interleaved gather: x[d] + sum x[src], transposed store ----
#pragma unroll 1
        for (int np = 0; np < 8; np++) {
            int nA = nb + 2 * np, nB = nA + 1;
            int degA = min(__ldg(&g_ideg[nA]), MAXDEG);
            int degB = min(__ldg(&g_ideg[nB]), MAXDEG);
            float aA0, aA1, aB0, aB1;
            gather_pair(xfeat, nA, nB, degA, degB, lane, aA0, aA1, aB0, aB1);
            xsf[lane * 20 + 2 * np] = aA0;
            xsf[(lane + 32) * 20 + 2 * np] = aA1;
            xsf[lane * 20 + 2 * np + 1] = aB0;
            xsf[(lane + 32) * 20 + 2 * np + 1] = aB1;
        }
        __syncwarp();

        // ---- layer a: K=64, 32 hidden (lane = hidden) ----
        u64 acc[8];
#pragma unroll
        for (int i = 0; i < 8; i++) acc[i] = bA;
#pragma unroll 4
        for (int k = 0; k < 64; k++) {
            const ulonglong2* row = (const ulonglong2*)(xs + k * ROW_U64);
            float w = sWa[k * 32 + lane];
            u64 wd = pk2(w, w);
#pragma unroll
            for (int q = 0; q < 4; q++) {
                ulonglong2 x2 = row[q];
                acc[2 * q]     = ffma2(x2.x, wd, acc[2 * q]);
                acc[2 * q + 1] = ffma2(x2.y, wd, acc[2 * q + 1]);
            }
        }
        __syncwarp();
        {
            u64* trow = xs + lane * ROW_U64;   // rows 0..31 = hidden
#pragma unroll
            for (int q = 0; q < 8; q++) trow[q] = relu2(acc[q]);
        }
        __syncwarp();

        // ---- layer b: K=32, 64 out (lane = f and f+32) ----
        u64 aO[8], aP[8];
#pragma unroll
        for (int i = 0; i < 8; i++) { aO[i] = bbL; aP[i] = bbH; }
#pragma unroll 4
        for (int k = 0; k < 32; k++) {
            const ulonglong2* row = (const ulonglong2*)(xs + k * ROW_U64);
            float wl = sWb[k * 64 + lane], wh = sWb[k * 64 + lane + 32];
            u64 wld = pk2(wl, wl), whd = pk2(wh, wh);
#pragma unroll
            for (int q = 0; q < 4; q++) {
                ulonglong2 x2 = row[q];
                aO[2 * q]     = ffma2(x2.x, wld, aO[2 * q]);
                aO[2 * q + 1] = ffma2(x2.y, wld, aO[2 * q + 1]);
                aP[2 * q]     = ffma2(x2.x, whd, aP[2 * q]);
                aP[2 * q + 1] = ffma2(x2.y, whd, aP[2 * q + 1]);
            }
        }

        // ---- epilogue: relu, store h1, stats ----
#pragma unroll
        for (int p = 0; p < 8; p++) {
            u64 O = relu2(aO[p]), P = relu2(aP[p]);
            float lo, hi, lo2, hi2;
            upk2(O, lo, hi); upk2(P, lo2, hi2);
            int n0 = nb + 2 * p;
            g_h1[n0 * 64 + lane] = lo;
            g_h1[(n0 + 1) * 64 + lane] = hi;
            g_h1[n0 * 64 + 32 + lane] = lo2;
            g_h1[(n0 + 1) * 64 + 32 + lane] = hi2;
            sA = add2(sA, O); qA = ffma2(O, O, qA);
            sB = add2(sB, P); qB = ffma2(P, P, qB);
        }
        __syncwarp();
    }

    float a, b;
    upk2(sA, a, b); atomicAdd(&g_stats1[lane], a + b);
    upk2(sB, a, b); atomicAdd(&g_stats1[lane + 32], a + b);
    upk2(qA, a, b); atomicAdd(&g_stats1[64 + lane], a + b);
    upk2(qB, a, b); atomicAdd(&g_stats1[96 + lane], a + b);
}

// ---------------- MLP2: fused gather + BN1 affine + 64->64->64 + pooling -----
__global__ __launch_bounds__(256, 3) void mlp2_kernel(
    const float* __restrict__ W2a, const float* __restrict__ b2a,
    const float* __restrict__ W2b, const float* __restrict__ b2b,
    const int* __restrict__ batch,
    const float* __restrict__ gamma1, const float* __restrict__ beta1) {
    extern __shared__ u64 sm[];
    u64* tables = sm;
    float* sWa = (float*)(sm + 8 * TBL_U64);   // 4096 f32
    float* sWb = sWa + 4096;                   // 4096 f32

    for (int i = threadIdx.x; i < 4096; i += 256) {
        sWa[i] = W2a[i];
        sWb[i] = W2b[i];
    }
    __syncthreads();

    int lane = threadIdx.x & 31;
    u64* xs = tables + (threadIdx.x >> 5) * TBL_U64;
    float* xsf = (float*)xs;

    // BN1 folded affine computed from stats (no finalize1 kernel)
    float aLo, aHi, bLo, bHi;
    {
        float m = g_stats1[lane] * (1.f / NN);
        float v = g_stats1[64 + lane] * (1.f / NN) - m * m;
        aLo = gamma1[lane] * rsqrtf(v + BN_EPS);
        bLo = beta1[lane] - m * aLo;
        float m2 = g_stats1[lane + 32] * (1.f / NN);
        float v2 = g_stats1[96 + lane] * (1.f / NN) - m2 * m2;
        aHi = gamma1[lane + 32] * rsqrtf(v2 + BN_EPS);
        bHi = beta1[lane + 32] - m2 * aHi;
    }

    int warp = (blockIdx.x * 256 + threadIdx.x) >> 5;
    int nw = (gridDim.x * 256) >> 5;

    float al = b2a[lane], ah = b2a[lane + 32];
    u64 baL = pk2(al, al), baH = pk2(ah, ah);
    float bl = b2b[lane], bh = b2b[lane + 32];
    u64 bbL = pk2(bl, bl), bbH = pk2(bh, bh);

    u64 sA = 0, sB = 0, qA = 0, qB = 0;
    u64 pA = 0, pB = 0;
    float crun = 0.f;
    int cg = -1;

    for (int t = warp; t < NTILES; t += nw) {
        int nb = t * TILE_N;
        // ---- interleaved gather over h1 + BN1 affine, transposed store ----
        const float* feat = (const float*)g_h1;
#pragma unroll 1
        for (int np = 0; np < 8; np++) {
            int nA = nb + 2 * np, nB = nA + 1;
            int degA = min(__ldg(&g_ideg[nA]), MAXDEG);
            int degB = min(__ldg(&g_ideg[nB]), MAXDEG);
            float aA0, aA1, aB0, aB1;
            gather_pair(feat, nA, nB, degA, degB, lane, aA0, aA1, aB0, aB1);
            float dgA = 1.f + (float)degA;
            float dgB = 1.f + (float)degB;
            xsf[lane * 20 + 2 * np] = fmaf(dgA, bLo, aLo * aA0);
            xsf[(lane + 32) * 20 + 2 * np] = fmaf(dgA, bHi, aHi * aA1);
            xsf[lane * 20 + 2 * np + 1] = fmaf(dgB, bLo, aLo * aB0);
            xsf[(lane + 32) * 20 + 2 * np + 1] = fmaf(dgB, bHi, aHi * aB1);
        }
        __syncwarp();

        // ---- layer a: K=64, 64 out ----
        u64 aO[8], aP[8];
#pragma unroll
        for (int i = 0; i < 8; i++) { aO[i] = baL; aP[i] = baH; }
#pragma unroll 4
        for (int k = 0; k < 64; k++) {
            const ulonglong2* row = (const ulonglong2*)(xs + k * ROW_U64);
            float wl = sWa[k * 64 + lane], wh = sWa[k * 64 + lane + 32];
            u64 wld = pk2(wl, wl), whd = pk2(wh, wh);
#pragma unroll
            for (int q = 0; q < 4; q++) {
                ulonglong2 x2 = row[q];
                aO[2 * q]     = ffma2(x2.x, wld, aO[2 * q]);
                aO[2 * q + 1] = ffma2(x2.y, wld, aO[2 * q + 1]);
                aP[2 * q]     = ffma2(x2.x, whd, aP[2 * q]);
                aP[2 * q + 1] = ffma2(x2.y, whd, aP[2 * q + 1]);
            }
        }
        __syncwarp();
        {
            u64* r0 = xs + lane * ROW_U64;
            u64* r1 = xs + (lane + 32) * ROW_U64;
#pragma unroll
            for (int q = 0; q < 8; q++) { r0[q] = relu2(aO[q]); r1[q] = relu2(aP[q]); }
        }
        __syncwarp();

        // ---- layer b: K=64, 64 out ----
#pragma unroll
        for (int i = 0; i < 8; i++) { aO[i] = bbL; aP[i] = bbH; }
#pragma unroll 4
        for (int k = 0; k < 64; k++) {
            const ulonglong2* row = (const ulonglong2*)(xs + k * ROW_U64);
            float wl = sWb[k * 64 + lane], wh = sWb[k * 64 + lane + 32];
            u64 wld = pk2(wl, wl), whd = pk2(wh, wh);
#pragma unroll
            for (int q = 0; q < 4; q++) {
                ulonglong2 x2 = row[q];
                aO[2 * q]     = ffma2(x2.x, wld, aO[2 * q]);
                aO[2 * q + 1] = ffma2(x2.y, wld, aO[2 * q + 1]);
                aP[2 * q]     = ffma2(x2.x, whd, aP[2 * q]);
                aP[2 * q + 1] = ffma2(x2.y, whd, aP[2 * q + 1]);
            }
        }

        // ---- epilogue: relu, stats, run-length pooling ----
#pragma unroll
        for (int p = 0; p < 8; p++) {
            u64 O = relu2(aO[p]), P = relu2(aP[p]);
            sA = add2(sA, O); qA = ffma2(O, O, qA);
            sB = add2(sB, P); qB = ffma2(P, P, qB);

            int2 bp = *((const int2*)(batch + nb + 2 * p));
            if (bp.x == cg && bp.y == cg) {
                pA = add2(pA, O); pB = add2(pB, P); crun += 2.f;
            } else {
                if (cg >= 0 && crun > 0.f) {
                    float a, b;
                    upk2(pA, a, b); atomicAdd(&g_gsum[cg * 64 + lane], a + b);
                    upk2(pB, a, b); atomicAdd(&g_gsum[cg * 64 + lane + 32], a + b);
                    if (lane == 0) atomicAdd(&g_cnt[cg], crun);
                }
                if (bp.x == bp.y) {
                    cg = bp.x; pA = O; pB = P; crun = 2.f;
                } else {
                    float a, b;
                    upk2(O, a, b);
                    atomicAdd(&g_gsum[bp.x * 64 + lane], a);
                    u64 tA = pk2(0.f, b);
                    upk2(P, a, b);
                    atomicAdd(&g_gsum[bp.x * 64 + lane + 32], a);
                    if (lane == 0) atomicAdd(&g_cnt[bp.x], 1.f);
                    cg = bp.y; pA = tA; pB = pk2(0.f, b); crun = 1.f;
                }
            }
        }
        __syncwarp();
    }
    if (cg >= 0 && crun > 0.f) {
        float a, b;
        upk2(pA, a, b); atomicAdd(&g_gsum[cg * 64 + lane], a + b);
        upk2(pB, a, b); atomicAdd(&g_gsum[cg * 64 + lane + 32], a + b);
        if (lane == 0) atomicAdd(&g_cnt[cg], crun);
    }
    float a, b;
    upk2(sA, a, b); atomicAdd(&g_stats2[lane], a + b);
    upk2(sB, a, b); atomicAdd(&g_stats2[lane + 32], a + b);
    upk2(qA, a, b); atomicAdd(&g_stats2[64 + lane], a + b);
    upk2(qB, a, b); atomicAdd(&g_stats2[96 + lane], a + b);
}

__global__ void finalize2_kernel(const float* __restrict__ gamma,
                                 const float* __restrict__ beta,
                                 float* __restrict__ out) {
    int f = threadIdx.x;
    int g = blockIdx.x;
    float mean = g_stats2[f] * (1.f / NN);
    float var = g_stats2[64 + f] * (1.f / NN) - mean * mean;
    float inv = rsqrtf(var + BN_EPS);
    float cnt = fmaxf(g_cnt[g], 1.f);
    float m = g_gsum[g * 64 + f] / cnt;
    out[g * 64 + f] = (m - mean) * inv * gamma[f] + beta[f];
}

// ---------------- launch -----------------------------------------------------
extern "C" void kernel_launch(void* const* d_in, const int* in_sizes, int n_in,
                              void* d_out, int out_size) {
    const float* x = (const float*)d_in[0];
    const int* ei = (const int*)d_in[1];
    const int* batch = (const int*)d_in[2];

    int base = 3;
    while (base < n_in && in_sizes[base] == 1) base++;
    const float* W1a = (const float*)d_in[base + 0];
    const float* b1a = (const float*)d_in[base + 1];
    const float* W1b = (const float*)d_in[base + 2];
    const float* b1b = (const float*)d_in[base + 3];
    const float* g1  = (const float*)d_in[base + 4];
    const float* be1 = (const float*)d_in[base + 5];
    const float* W2a = (const float*)d_in[base + 6];
    const float* b2a = (const float*)d_in[base + 7];
    const float* W2b = (const float*)d_in[base + 8];
    const float* b2b = (const float*)d_in[base + 9];
    const float* g2  = (const float*)d_in[base + 10];
    const float* be2 = (const float*)d_in[base + 11];
    float* out = (float*)d_out;

    const int smem1 = 8 * TBL_U64 * 8 + 2 * 2048 * 4;   // 40960 + 16384 = 57344
    const int smem2 = 8 * TBL_U64 * 8 + 2 * 4096 * 4;   // 40960 + 32768 = 73728
    cudaFuncSetAttribute(mlp1_kernel, cudaFuncAttributeMaxDynamicSharedMemorySize, smem1);
    cudaFuncSetAttribute(mlp2_kernel, cudaFuncAttributeMaxDynamicSharedMemorySize, smem2);

    zero_kernel<<<(NN + 255) / 256, 256>>>();
    adj_build_kernel<<<NE / 256, 256>>>(ei);
    mlp1_kernel<<<592, 256, smem1>>>(x, W1a, b1a, W1b, b1b);
    mlp2_kernel<<<444, 256, smem2>>>(W2a, b2a, W2b, b2b, batch, g1, be1);
    finalize2_kernel<<<NG, 64>>>(g2, be2, out);
}

// round 16
// speedup vs baseline: 1.5643x; 1.5643x over previous
#include <cuda_runtime.h>

#define NN 100000
#define NE 1600000
#define NG 16
#define PERG (NE / NG)      // 100000 edges per graph segment
#define TSTEP (NN / NG)     // 6250 threshold step
#define BN_EPS 1e-5f
#define MAXDEG 64
#define FULLMASK 0xffffffffu

typedef unsigned long long u64;

// ---------------- scratch ----------------------------------------------------
__device__ float g_h1[NN * 64];     // MLP1 output (post-relu, pre-BN)
__device__ int   g_adj[NN * MAXDEG];
__device__ int   g_ideg[NN];
__device__ float g_stats1[128];
__device__ float g_stats2[128];
__device__ float g_gsum[NG * 64];
__device__ float g_cnt[NG];

// ---------------- helpers ----------------------------------------------------
__device__ __forceinline__ u64 pk2(float lo, float hi) {
    u64 r; asm("mov.b64 %0, {%1,%2};" : "=l"(r) : "f"(lo), "f"(hi)); return r;
}
__device__ __forceinline__ void upk2(u64 v, float& a, float& b) {
    asm("mov.b64 {%0,%1}, %2;" : "=f"(a), "=f"(b) : "l"(v));
}
__device__ __forceinline__ u64 ffma2(u64 a, u64 b, u64 c) {
    u64 d; asm("fma.rn.f32x2 %0, %1, %2, %3;" : "=l"(d) : "l"(a), "l"(b), "l"(c));
    return d;
}
__device__ __forceinline__ u64 add2(u64 a, u64 b) {
    u64 d; asm("add.rn.f32x2 %0, %1, %2;" : "=l"(d) : "l"(a), "l"(b));
    return d;
}
__device__ __forceinline__ u64 relu2(u64 v) {
    float a, b; upk2(v, a, b);
    return pk2(fmaxf(a, 0.f), fmaxf(b, 0.f));
}

// Table: per warp, 64 rows x 6 u64 (8 nodes = 4 pairs data + 2 pad u64,
// stride 12 floats -> rows 16B-aligned for LDS.128 broadcast reads).
#define ROW_U64 6
#define TBL_U64 (64 * ROW_U64)          // 384 u64 per warp (3 KB)
#define TILE_N 8
#define NTILES (NN / TILE_N)            // 12500 exact

// ---------------- small kernels ----------------------------------------------
__global__ void zero_kernel() {
    int i = blockIdx.x * blockDim.x + threadIdx.x;
    if (i < NN) g_ideg[i] = 0;
    if (i < 128) { g_stats1[i] = 0.f; g_stats2[i] = 0.f; }
    if (i < NG * 64) g_gsum[i] = 0.f;
    if (i < NG) g_cnt[i] = 0.f;
}

__global__ void adj_build_kernel(const int* __restrict__ ei) {
    int e = blockIdx.x * blockDim.x + threadIdx.x;
    if (e >= NE) return;
    int th = (e / PERG) * TSTEP;
    int s = __ldg(&ei[e]);
    int d = __ldg(&ei[NE + e]);
    if (s < th || d < th) return;
    int slot = atomicAdd(&g_ideg[d], 1);
    if (slot < MAXDEG) g_adj[d * MAXDEG + slot] = s;
}

// ---------------- MLP1 (fused gather): 64 -> relu 32 -> relu 64 --------------
__global__ __launch_bounds__(256, 4) void mlp1_kernel(
    const float* __restrict__ xfeat,
    const float* __restrict__ W1a, const float* __restrict__ b1a,
    const float* __restrict__ W1b, const float* __restrict__ b1b) {
    extern __shared__ u64 sm[];
    u64* tables = sm;                          // 8 * 384 u64 (24 KB)
    float* sWa = (float*)(sm + 8 * TBL_U64);   // 2048 f32
    float* sWb = sWa + 2048;                   // 2048 f32

    for (int i = threadIdx.x; i < 2048; i += 256) {
        sWa[i] = W1a[i];
        sWb[i] = W1b[i];
    }
    __syncthreads();

    int lane = threadIdx.x & 31;
    u64* xs = tables + (threadIdx.x >> 5) * TBL_U64;
    float* xsf = (float*)xs;

    int warp = (blockIdx.x * 256 + threadIdx.x) >> 5;
    int nw = (gridDim.x * 256) >> 5;

    float bav = b1a[lane];
    u64 bA = pk2(bav, bav);
    float bl = b1b[lane], bh = b1b[lane + 32];
    u64 bbL = pk2(bl, bl), bbH = pk2(bh, bh);

    u64 sA = 0, sB = 0, qA = 0, qB = 0;

    for (int t = warp; t < NTILES; t += nw) {
        int nb = t * TILE_N;
        // ---- fused gather: x[d] + sum x[src], transposed store ----
#pragma unroll 1
        for (int n = 0; n < TILE_N; n++) {
            int node = nb + n;
            int deg = min(__ldg(&g_ideg[node]), MAXDEG);
            const int* adj = g_adj + node * MAXDEG;
            const float* self = xfeat + node * 64;
            float a0 = __ldg(&self[lane]);
            float a1 = __ldg(&self[lane + 32]);
            float t0 = 0.f, t1 = 0.f, t2 = 0.f, t3 = 0.f;
            int j = 0;
            for (; j + 2 <= deg; j += 2) {
                int s0 = __ldg(&adj[j]), s1 = __ldg(&adj[j + 1]);
                const float* r0 = xfeat + s0 * 64;
                const float* r1 = xfeat + s1 * 64;
                t0 += __ldg(&r0[lane]);
                t1 += __ldg(&r1[lane]);
                t2 += __ldg(&r0[lane + 32]);
                t3 += __ldg(&r1[lane + 32]);
            }
            if (j < deg) {
                const float* r0 = xfeat + __ldg(&adj[j]) * 64;
                t0 += __ldg(&r0[lane]);
                t2 += __ldg(&r0[lane + 32]);
            }
            a0 += t0 + t1;
            a1 += t2 + t3;
            xsf[lane * 12 + n] = a0;
            xsf[(lane + 32) * 12 + n] = a1;
        }
        __syncwarp();

        // ---- layer a: K=64, 32 hidden (lane = hidden) ----
        u64 acc[4];
#pragma unroll
        for (int i = 0; i < 4; i++) acc[i] = bA;
#pragma unroll 4
        for (int k = 0; k < 64; k++) {
            const ulonglong2* row = (const ulonglong2*)(xs + k * ROW_U64);
            float w = sWa[k * 32 + lane];
            u64 wd = pk2(w, w);
            ulonglong2 x01 = row[0], x23 = row[1];
            acc[0] = ffma2(x01.x, wd, acc[0]);
            acc[1] = ffma2(x01.y, wd, acc[1]);
            acc[2] = ffma2(x23.x, wd, acc[2]);
            acc[3] = ffma2(x23.y, wd, acc[3]);
        }
        __syncwarp();
        {
            u64* trow = xs + lane * ROW_U64;   // rows 0..31 = hidden
#pragma unroll
            for (int q = 0; q < 4; q++) trow[q] = relu2(acc[q]);
        }
        __syncwarp();

        // ---- layer b: K=32, 64 out (lane = f and f+32) ----
        u64 aO[4], aP[4];
#pragma unroll
        for (int i = 0; i < 4; i++) { aO[i] = bbL; aP[i] = bbH; }
#pragma unroll 4
        for (int k = 0; k < 32; k++) {
            const ulonglong2* row = (const ulonglong2*)(xs + k * ROW_U64);
            float wl = sWb[k * 64 + lane], wh = sWb[k * 64 + lane + 32];
            u64 wld = pk2(wl, wl), whd = pk2(wh, wh);
            ulonglong2 x01 = row[0], x23 = row[1];
            aO[0] = ffma2(x01.x, wld, aO[0]);
            aO[1] = ffma2(x01.y, wld, aO[1]);
            aO[2] = ffma2(x23.x, wld, aO[2]);
            aO[3] = ffma2(x23.y, wld, aO[3]);
            aP[0] = ffma2(x01.x, whd, aP[0]);
            aP[1] = ffma2(x01.y, whd, aP[1]);
            aP[2] = ffma2(x23.x, whd, aP[2]);
            aP[3] = ffma2(x23.y, whd, aP[3]);
        }

        // ---- epilogue: relu, store h1, stats ----
#pragma unroll
        for (int p = 0; p < 4; p++) {
            u64 O = relu2(aO[p]), P = relu2(aP[p]);
            float lo, hi, lo2, hi2;
            upk2(O, lo, hi); upk2(P, lo2, hi2);
            int n0 = nb + 2 * p;
            g_h1[n0 * 64 + lane] = lo;
            g_h1[(n0 + 1) * 64 + lane] = hi;
            g_h1[n0 * 64 + 32 + lane] = lo2;
            g_h1[(n0 + 1) * 64 + 32 + lane] = hi2;
            sA = add2(sA, O); qA = ffma2(O, O, qA);
            sB = add2(sB, P); qB = ffma2(P, P, qB);
        }
        __syncwarp();
    }

    float a, b;
    upk2(sA, a, b); atomicAdd(&g_stats1[lane], a + b);
    upk2(sB, a, b); atomicAdd(&g_stats1[lane + 32], a + b);
    upk2(qA, a, b); atomicAdd(&g_stats1[64 + lane], a + b);
    upk2(qB, a, b); atomicAdd(&g_stats1[96 + lane], a + b);
}

// ---------------- MLP2: fused gather + BN1 affine + 64->64->64 + pooling -----
__global__ __launch_bounds__(256, 4) void mlp2_kernel(
    const float* __restrict__ W2a, const float* __restrict__ b2a,
    const float* __restrict__ W2b, const float* __restrict__ b2b,
    const int* __restrict__ batch,
    const float* __restrict__ gamma1, const float* __restrict__ beta1) {
    extern __shared__ u64 sm[];
    u64* tables = sm;                          // 8 * 384 u64 (24 KB)
    float* sWa = (float*)(sm + 8 * TBL_U64);   // 4096 f32
    float* sWb = sWa + 4096;                   // 4096 f32

    for (int i = threadIdx.x; i < 4096; i += 256) {
        sWa[i] = W2a[i];
        sWb[i] = W2b[i];
    }
    __syncthreads();

    int lane = threadIdx.x & 31;
    u64* xs = tables + (threadIdx.x >> 5) * TBL_U64;
    float* xsf = (float*)xs;

    // BN1 folded affine computed from stats (no finalize1 kernel)
    float aLo, aHi, bLo, bHi;
    {
        float m = g_stats1[lane] * (1.f / NN);
        float v = g_stats1[64 + lane] * (1.f / NN) - m * m;
        aLo = gamma1[lane] * rsqrtf(v + BN_EPS);
        bLo = beta1[lane] - m * aLo;
        float m2 = g_stats1[lane + 32] * (1.f / NN);
        float v2 = g_stats1[96 + lane] * (1.f / NN) - m2 * m2;
        aHi = gamma1[lane + 32] * rsqrtf(v2 + BN_EPS);
        bHi = beta1[lane + 32] - m2 * aHi;
    }

    int warp = (blockIdx.x * 256 + threadIdx.x) >> 5;
    int nw = (gridDim.x * 256) >> 5;

    float al = b2a[lane], ah = b2a[lane + 32];
    u64 baL = pk2(al, al), baH = pk2(ah, ah);
    float bl = b2b[lane], bh = b2b[lane + 32];
    u64 bbL = pk2(bl, bl), bbH = pk2(bh, bh);

    u64 sA = 0, sB = 0, qA = 0, qB = 0;
    u64 pA = 0, pB = 0;
    float crun = 0.f;
    int cg = -1;

    for (int t = warp; t < NTILES; t += nw) {
        int nb = t * TILE_N;
        // ---- fused gather over h1 + BN1 affine, transposed store ----
        const float* feat = (const float*)g_h1;
#pragma unroll 1
        for (int n = 0; n < TILE_N; n++) {
            int node = nb + n;
            int deg = min(__ldg(&g_ideg[node]), MAXDEG);
            const int* adj = g_adj + node * MAXDEG;
            const float* self = feat + node * 64;
            float a0 = __ldg(&self[lane]);
            float a1 = __ldg(&self[lane + 32]);
            float t0 = 0.f, t1 = 0.f, t2 = 0.f, t3 = 0.f;
            int j = 0;
            for (; j + 2 <= deg; j += 2) {
                int s0 = __ldg(&adj[j]), s1 = __ldg(&adj[j + 1]);
                const float* r0 = feat + s0 * 64;
                const float* r1 = feat + s1 * 64;
                t0 += __ldg(&r0[lane]);
                t1 += __ldg(&r1[lane]);
                t2 += __ldg(&r0[lane + 32]);
                t3 += __ldg(&r1[lane + 32]);
            }
            if (j < deg) {
                const float* r0 = feat + __ldg(&adj[j]) * 64;
                t0 += __ldg(&r0[lane]);
                t2 += __ldg(&r0[lane + 32]);
            }
            a0 += t0 + t1;
            a1 += t2 + t3;
            float dg = 1.f + (float)deg;
            xsf[lane * 12 + n] = fmaf(dg, bLo, aLo * a0);
            xsf[(lane + 32) * 12 + n] = fmaf(dg, bHi, aHi * a1);
        }
        __syncwarp();

        // ---- layer a: K=64, 64 out ----
        u64 aO[4], aP[4];
#pragma unroll
        for (int i = 0; i < 4; i++) { aO[i] = baL; aP[i] = baH; }
#pragma unroll 4
        for (int k = 0; k < 64; k++) {
            const ulonglong2* row = (const ulonglong2*)(xs + k * ROW_U64);
            float wl = sWa[k * 64 + lane], wh = sWa[k * 64 + lane + 32];
            u64 wld = pk2(wl, wl), whd = pk2(wh, wh);
            ulonglong2 x01 = row[0], x23 = row[1];
            aO[0] = ffma2(x01.x, wld, aO[0]);
            aO[1] = ffma2(x01.y, wld, aO[1]);
            aO[2] = ffma2(x23.x, wld, aO[2]);
            aO[3] = ffma2(x23.y, wld, aO[3]);
            aP[0] = ffma2(x01.x, whd, aP[0]);
            aP[1] = ffma2(x01.y, whd, aP[1]);
            aP[2] = ffma2(x23.x, whd, aP[2]);
            aP[3] = ffma2(x23.y, whd, aP[3]);
        }
        __syncwarp();
        {
            u64* r0 = xs + lane * ROW_U64;
            u64* r1 = xs + (lane + 32) * ROW_U64;
#pragma unroll
            for (int q = 0; q < 4; q++) { r0[q] = relu2(aO[q]); r1[q] = relu2(aP[q]); }
        }
        __syncwarp();

        // ---- layer b: K=64, 64 out ----
#pragma unroll
        for (int i = 0; i < 4; i++) { aO[i] = bbL; aP[i] = bbH; }
#pragma unroll 4
        for (int k = 0; k < 64; k++) {
            const ulonglong2* row = (const ulonglong2*)(xs + k * ROW_U64);
            float wl = sWb[k * 64 + lane], wh = sWb[k * 64 + lane + 32];
            u64 wld = pk2(wl, wl), whd = pk2(wh, wh);
            ulonglong2 x01 = row[0], x23 = row[1];
            aO[0] = ffma2(x01.x, wld, aO[0]);
            aO[1] = ffma2(x01.y, wld, aO[1]);
            aO[2] = ffma2(x23.x, wld, aO[2]);
            aO[3] = ffma2(x23.y, wld, aO[3]);
            aP[0] = ffma2(x01.x, whd, aP[0]);
            aP[1] = ffma2(x01.y, whd, aP[1]);
            aP[2] = ffma2(x23.x, whd, aP[2]);
            aP[3] = ffma2(x23.y, whd, aP[3]);
        }

        // ---- epilogue: relu, stats, run-length pooling ----
#pragma unroll
        for (int p = 0; p < 4; p++) {
            u64 O = relu2(aO[p]), P = relu2(aP[p]);
            sA = add2(sA, O); qA = ffma2(O, O, qA);
            sB = add2(sB, P); qB = ffma2(P, P, qB);

            int2 bp = *((const int2*)(batch + nb + 2 * p));
            if (bp.x == cg && bp.y == cg) {
                pA = add2(pA, O); pB = add2(pB, P); crun += 2.f;
            } else {
                if (cg >= 0 && crun > 0.f) {
                    float a, b;
                    upk2(pA, a, b); atomicAdd(&g_gsum[cg * 64 + lane], a + b);
                    upk2(pB, a, b); atomicAdd(&g_gsum[cg * 64 + lane + 32], a + b);
                    if (lane == 0) atomicAdd(&g_cnt[cg], crun);
                }
                if (bp.x == bp.y) {
                    cg = bp.x; pA = O; pB = P; crun = 2.f;
                } else {
                    float a, b;
                    upk2(O, a, b);
                    atomicAdd(&g_gsum[bp.x * 64 + lane], a);
                    u64 tA = pk2(0.f, b);
                    upk2(P, a, b);
                    atomicAdd(&g_gsum[bp.x * 64 + lane + 32], a);
                    if (lane == 0) atomicAdd(&g_cnt[bp.x], 1.f);
                    cg = bp.y; pA = tA; pB = pk2(0.f, b); crun = 1.f;
                }
            }
        }
        __syncwarp();
    }
    if (cg >= 0 && crun > 0.f) {
        float a, b;
        upk2(pA, a, b); atomicAdd(&g_gsum[cg * 64 + lane], a + b);
        upk2(pB, a, b); atomicAdd(&g_gsum[cg * 64 + lane + 32], a + b);
        if (lane == 0) atomicAdd(&g_cnt[cg], crun);
    }
    float a, b;
    upk2(sA, a, b); atomicAdd(&g_stats2[lane], a + b);
    upk2(sB, a, b); atomicAdd(&g_stats2[lane + 32], a + b);
    upk2(qA, a, b); atomicAdd(&g_stats2[64 + lane], a + b);
    upk2(qB, a, b); atomicAdd(&g_stats2[96 + lane], a + b);
}

__global__ void finalize2_kernel(const float* __restrict__ gamma,
                                 const float* __restrict__ beta,
                                 float* __restrict__ out) {
    int f = threadIdx.x;
    int g = blockIdx.x;
    float mean = g_stats2[f] * (1.f / NN);
    float var = g_stats2[64 + f] * (1.f / NN) - mean * mean;
    float inv = rsqrtf(var + BN_EPS);
    float cnt = fmaxf(g_cnt[g], 1.f);
    float m = g_gsum[g * 64 + f] / cnt;
    out[g * 64 + f] = (m - mean) * inv * gamma[f] + beta[f];
}

// ---------------- launch -----------------------------------------------------
extern "C" void kernel_launch(void* const* d_in, const int* in_sizes, int n_in,
                              void* d_out, int out_size) {
    const float* x = (const float*)d_in[0];
    const int* ei = (const int*)d_in[1];
    const int* batch = (const int*)d_in[2];

    int base = 3;
    while (base < n_in && in_sizes[base] == 1) base++;
    const float* W1a = (const float*)d_in[base + 0];
    const float* b1a = (const float*)d_in[base + 1];
    const float* W1b = (const float*)d_in[base + 2];
    const float* b1b = (const float*)d_in[base + 3];
    const float* g1  = (const float*)d_in[base + 4];
    const float* be1 = (const float*)d_in[base + 5];
    const float* W2a = (const float*)d_in[base + 6];
    const float* b2a = (const float*)d_in[base + 7];
    const float* W2b = (const float*)d_in[base + 8];
    const float* b2b = (const float*)d_in[base + 9];
    const float* g2  = (const float*)d_in[base + 10];
    const float* be2 = (const float*)d_in[base + 11];
    float* out = (float*)d_out;

    const int smem1 = 8 * TBL_U64 * 8 + 2 * 2048 * 4;   // 24576 + 16384 = 40960
    const int smem2 = 8 * TBL_U64 * 8 + 2 * 4096 * 4;   // 24576 + 32768 = 57344
    cudaFuncSetAttribute(mlp1_kernel, cudaFuncAttributeMaxDynamicSharedMemorySize, smem1);
    cudaFuncSetAttribute(mlp2_kernel, cudaFuncAttributeMaxDynamicSharedMemorySize, smem2);

    zero_kernel<<<(NN + 255) / 256, 256>>>();
    adj_build_kernel<<<NE / 256, 256>>>(ei);
    mlp1_kernel<<<592, 256, smem1>>>(x, W1a, b1a, W1b, b1b);
    mlp2_kernel<<<592, 256, smem2>>>(W2a, b2a, W2b, b2b, batch, g1, be1);
    finalize2_kernel<<<NG, 64>>>(g2, be2, out);
}